// round 17
// baseline (speedup 1.0000x reference)
#include <cuda_runtime.h>

#define BATCH   32
#define D_IN    1024
#define D_OUT   1024
#define E_DIM   3076                 // D_OUT + 2*D_IN + 4
#define NRB     147                  // row blocks; block NRB = server
#define WPB     14                   // row warps per block
#define GWN     (NRB * WPB)          // 2058 row-warps
#define KQ_TOTAL 2052u               // rows with e >= D_OUT
#define SMEM_BYTES (WPB * 2 * 1024 * 4)   // 114688: per warp 2 x 1024 floats

// Scratch + sync (allocation-free rule: __device__ globals)
__device__ float    g_out [BATCH * E_DIM];   // only e >= D_OUT consumed
__device__ float    g_kphi[BATCH * D_IN];
__device__ float    g_qphi[BATCH * D_IN];
__device__ float    g_sig [BATCH * 4];
__device__ unsigned g_cnt [BATCH];
__device__ unsigned g_flag[BATCH];

__global__ void srwm_init()
{
    for (int i = 0; i < BATCH; i++) { g_cnt[i] = 0; g_flag[i] = 0; }
}

// ---------------------------------------------------------------------------
// One-warp softmax over 1024 values (server block).
// ---------------------------------------------------------------------------
__device__ __forceinline__ void softmax1024(const float* __restrict__ src,
                                            float* __restrict__ dst, int lane)
{
    float4 v[8];
    float m = -1e30f;
#pragma unroll
    for (int j = 0; j < 8; j++) {
        v[j] = __ldcg(((const float4*)src) + lane + j * 32);
        m = fmaxf(m, fmaxf(fmaxf(v[j].x, v[j].y), fmaxf(v[j].z, v[j].w)));
    }
#pragma unroll
    for (int o = 16; o; o >>= 1) m = fmaxf(m, __shfl_xor_sync(0xffffffffu, m, o));
    float s = 0.f;
#pragma unroll
    for (int j = 0; j < 8; j++) {
        v[j].x = __expf(v[j].x - m); v[j].y = __expf(v[j].y - m);
        v[j].z = __expf(v[j].z - m); v[j].w = __expf(v[j].w - m);
        s += v[j].x + v[j].y + v[j].z + v[j].w;
    }
#pragma unroll
    for (int o = 16; o; o >>= 1) s += __shfl_xor_sync(0xffffffffu, s, o);
    const float inv = 1.0f / s;
#pragma unroll
    for (int j = 0; j < 8; j++) {
        float4 o4 = { v[j].x * inv, v[j].y * inv, v[j].z * inv, v[j].w * inv };
        ((float4*)dst)[lane + j * 32] = o4;
    }
}

// ---------------------------------------------------------------------------
// Fused persistent kernel. Blocks 0..146: row blocks, 14 warps each,
// warp-autonomous (no __syncthreads). Block 147: softmax/sigmoid server.
// Warp (bid,wid) owns row a = wid*147+bid (regs, double-buffered) and,
// if ea < 1018, row b = ea + 2058 (smem, double-buffered).
// ---------------------------------------------------------------------------
__global__ void __launch_bounds__(448, 1)
srwm_fused(const float* __restrict__ w, const float* __restrict__ x,
           float* __restrict__ y, float* __restrict__ wout, int write_y)
{
    extern __shared__ float smem[];
    const int tid  = threadIdx.x;
    const int wid  = tid >> 5;
    const int lane = tid & 31;
    const int bid  = blockIdx.x;

    if (bid == NRB) {
        // ---------------- softmax / sigmoid server ----------------
        if (wid > 2) return;
        for (int b = 0; b < BATCH; b++) {
            while (*(volatile unsigned*)&g_cnt[b] < KQ_TOTAL) __nanosleep(64);
            __threadfence();
            if (wid == 0) {
                softmax1024(g_out + (size_t)b * E_DIM + D_OUT,
                            g_kphi + (size_t)b * D_IN, lane);
            } else if (wid == 1) {
                softmax1024(g_out + (size_t)b * E_DIM + D_OUT + D_IN,
                            g_qphi + (size_t)b * D_IN, lane);
            } else {
                if (lane < 4) {
                    float t = __ldcg(&g_out[(size_t)b * E_DIM + D_OUT + 2 * D_IN + lane]);
                    g_sig[b * 4 + lane] = 1.0f / (1.0f + __expf(-t));
                }
            }
            __threadfence();
            if (lane == 0) atomicAdd(&g_flag[b], 1u);
        }
        return;
    }

    // ---------------- row warps ----------------
    const int  ea  = wid * NRB + bid;            // 0..2057, all valid
    const int  eb  = ea + GWN;                   // valid iff ea < 1018; always kq
    const bool hb  = (eb < E_DIM);
    const bool kqa = (ea >= D_OUT);
    const unsigned nkq = (kqa ? 1u : 0u) + (hb ? 1u : 0u);
    const int sega = (ea < D_OUT) ? 0 : (ea < D_OUT + D_IN) ? 1 : 2;  // ea < 2058
    const int segb = (eb < D_OUT + 2 * D_IN) ? 2 : 3;

    float* sb = smem + wid * 2048;               // 2 parity slots x 1024 floats

    float4 A[2][8];                              // row a, reg double buffer
    float4 T[8];                                 // row b staging

    // ---- load + dot one batch into parity p (front-batched LDG) ----
    auto load_dot = [&](int b, int p) {
        const float4* pa = (const float4*)(w + ((size_t)b * E_DIM + ea) * D_IN);
#pragma unroll
        for (int j = 0; j < 8; j++) A[p][j] = __ldcs(pa + lane + j * 32);
        if (hb) {
            const float4* pb = (const float4*)(w + ((size_t)b * E_DIM + eb) * D_IN);
#pragma unroll
            for (int j = 0; j < 8; j++) T[j] = __ldcs(pb + lane + j * 32);
        }
        const float4* x4 = (const float4*)(x + (size_t)b * D_IN);
        float acc = 0.f;
#pragma unroll
        for (int j = 0; j < 8; j++) {
            float4 xv = __ldg(x4 + lane + j * 32);
            acc += A[p][j].x * xv.x + A[p][j].y * xv.y +
                   A[p][j].z * xv.z + A[p][j].w * xv.w;
        }
#pragma unroll
        for (int o = 16; o; o >>= 1) acc += __shfl_xor_sync(0xffffffffu, acc, o);
        if (lane == 0) {
            if (kqa) g_out[(size_t)b * E_DIM + ea] = acc;
            else if (write_y) y[(size_t)b * D_OUT + ea] = acc;
        }
        if (hb) {
            float4* s4 = (float4*)(sb + p * 1024);
            float accb = 0.f;
#pragma unroll
            for (int j = 0; j < 8; j++) {
                s4[lane + j * 32] = T[j];
                float4 xv = __ldg(x4 + lane + j * 32);
                accb += T[j].x * xv.x + T[j].y * xv.y +
                        T[j].z * xv.z + T[j].w * xv.w;
            }
#pragma unroll
            for (int o = 16; o; o >>= 1) accb += __shfl_xor_sync(0xffffffffu, accb, o);
            if (lane == 0) g_out[(size_t)b * E_DIM + eb] = accb;
        }
        __threadfence();
        if (lane == 0 && nkq) atomicAdd(&g_cnt[b], nkq);
    };

    auto waitflag = [&](int b) {
        while (*(volatile unsigned*)&g_flag[b] < 3u) __nanosleep(64);
        __threadfence();
    };

    // ---- update batch b from parity p ----
    auto upd = [&](int b, int p) {
        const float4* kp = (const float4*)(g_kphi + (size_t)b * D_IN);
        const float4* qp = (const float4*)(g_qphi + (size_t)b * D_IN);

        // row a (registers)
        float ab = 0.f, av = 0.f;
#pragma unroll
        for (int j = 0; j < 8; j++) {
            float4 kv = __ldg(kp + lane + j * 32);
            float4 qv = __ldg(qp + lane + j * 32);
            ab += A[p][j].x * kv.x + A[p][j].y * kv.y + A[p][j].z * kv.z + A[p][j].w * kv.w;
            av += A[p][j].x * qv.x + A[p][j].y * qv.y + A[p][j].z * qv.z + A[p][j].w * qv.w;
        }
#pragma unroll
        for (int o = 16; o; o >>= 1) {
            ab += __shfl_xor_sync(0xffffffffu, ab, o);
            av += __shfl_xor_sync(0xffffffffu, av, o);
        }
        float coeff = __ldg(&g_sig[b * 4 + sega]) * (av - ab);
        float4* oa = (float4*)(wout + ((size_t)b * E_DIM + ea) * D_IN);
#pragma unroll
        for (int j = 0; j < 8; j++) {
            float4 kv = __ldg(kp + lane + j * 32);
            float4 o4 = { A[p][j].x + coeff * kv.x, A[p][j].y + coeff * kv.y,
                          A[p][j].z + coeff * kv.z, A[p][j].w + coeff * kv.w };
            __stcs(oa + lane + j * 32, o4);
        }

        if (hb) {
            // row b (smem)
            const float4* s4 = (const float4*)(sb + p * 1024);
#pragma unroll
            for (int j = 0; j < 8; j++) T[j] = s4[lane + j * 32];
            ab = 0.f; av = 0.f;
#pragma unroll
            for (int j = 0; j < 8; j++) {
                float4 kv = __ldg(kp + lane + j * 32);
                float4 qv = __ldg(qp + lane + j * 32);
                ab += T[j].x * kv.x + T[j].y * kv.y + T[j].z * kv.z + T[j].w * kv.w;
                av += T[j].x * qv.x + T[j].y * qv.y + T[j].z * qv.z + T[j].w * qv.w;
            }
#pragma unroll
            for (int o = 16; o; o >>= 1) {
                ab += __shfl_xor_sync(0xffffffffu, ab, o);
                av += __shfl_xor_sync(0xffffffffu, av, o);
            }
            float coeffb = __ldg(&g_sig[b * 4 + segb]) * (av - ab);
            float4* ob = (float4*)(wout + ((size_t)b * E_DIM + eb) * D_IN);
#pragma unroll
            for (int j = 0; j < 8; j++) {
                float4 kv = __ldg(kp + lane + j * 32);
                float4 o4 = { T[j].x + coeffb * kv.x, T[j].y + coeffb * kv.y,
                              T[j].z + coeffb * kv.z, T[j].w + coeffb * kv.w };
                __stcs(ob + lane + j * 32, o4);
            }
        }
    };

    // ---- pipelined main loop: post(b+1) precedes wait(b) -> deadlock-free ----
    load_dot(0, 0);
#pragma unroll 1
    for (int b = 0; b < BATCH; b++) {
        if (b + 1 < BATCH) load_dot(b + 1, (b + 1) & 1);
        waitflag(b);
        upd(b, b & 1);
    }
}

// ---------------------------------------------------------------------------
// kernel_launch: init + one fused kernel (2 graph nodes).
// ---------------------------------------------------------------------------
extern "C" void kernel_launch(void* const* d_in, const int* in_sizes, int n_in,
                              void* d_out, int out_size)
{
    const float* x = (const float*)d_in[0];
    const float* w = (const float*)d_in[1];
    if (n_in >= 2 && in_sizes[0] != BATCH * D_IN) {
        x = (const float*)d_in[1];
        w = (const float*)d_in[0];
    }

    const size_t wout_elems = (size_t)BATCH * E_DIM * D_IN;
    float* out = (float*)d_out;

    float* y_ptr    = out;
    float* wout_ptr = out + ((size_t)out_size - wout_elems);
    const int write_y = ((size_t)out_size > wout_elems) ? 1 : 0;

    static int configured = 0;
    if (!configured) {
        cudaFuncSetAttribute(srwm_fused,
                             cudaFuncAttributeMaxDynamicSharedMemorySize,
                             SMEM_BYTES);
        configured = 1;
    }

    srwm_init<<<1, 1>>>();
    srwm_fused<<<NRB + 1, 448, SMEM_BYTES>>>(w, x, y_ptr, wout_ptr, write_y);
}